// round 5
// baseline (speedup 1.0000x reference)
#include <cuda_runtime.h>
#include <cuda_fp16.h>

// ROI Align via fp16 NHWC relayout, half2 bilinear arithmetic.
//  Pass 1: NCHW fp32 (2,256,200,304) -> NHWC fp16 scratch (62 MB, L2-resident)
//  Pass 2: block = ROI. 8 warps; warp = one output position; lane = 8 channels
//          (uint4 = 4x half2). Per subsample: 4-corner weighted sum in half2
//          (HFMA2), converted once, accumulated fp32 across the 4 subsamples.
//          Outputs staged in smem in two position-chunks, flushed coalesced.

#define NCH   256
#define FH    200
#define FW    304
#define HW    (FH*FW)        // 60800
#define POUT  7
#define OPP   49
#define S14   14
#define SMP   260           // staging pitch (floats): 256 + 4

__device__ unsigned int g_nh[(size_t)2 * HW * (NCH/2)];   // fp16x2 NHWC, 62 MB

// ---------------- Pass 1: NCHW fp32 -> NHWC fp16 ----------------
__global__ void __launch_bounds__(256)
to_nhwc_h(const float* __restrict__ in)
{
    __shared__ float tile[32][65];
    const int b   = blockIdx.z;
    const int c0  = blockIdx.y * 64;
    const int hw0 = blockIdx.x * 32;
    const int tx  = threadIdx.x;            // 0..31 (hw)
    const int ty  = threadIdx.y;            // 0..7  (c)

    const float* src = in + (size_t)(b * NCH + c0) * HW + hw0;
#pragma unroll
    for (int k = 0; k < 8; k++)
        tile[tx][ty + 8*k] = src[(size_t)(ty + 8*k) * HW + tx];
    __syncthreads();

    unsigned int* dst = g_nh + (size_t)(b * HW + hw0) * (NCH/2) + (c0 >> 1);
#pragma unroll
    for (int i = 0; i < 4; i++) {
        int hw = i*8 + ty;
        __half2 h = __floats2half2_rn(tile[hw][2*tx], tile[hw][2*tx + 1]);
        dst[(size_t)hw * (NCH/2) + tx] = *(unsigned int*)&h;
    }
}

// ---------------- Pass 2 ----------------
__device__ __forceinline__ void axis_prep(float t, int size,
                                          int& lo, int& hi, float& frac,
                                          float& valid)
{
    valid = (t > -1.0f && t < (float)size) ? 1.0f : 0.0f;
    float tc  = (t < 0.0f) ? 0.0f : t;
    float low = floorf(tc);
    if (low >= (float)(size - 1)) {
        lo = size - 1; hi = size - 1; frac = 0.0f;
    } else {
        lo = (int)low; hi = lo + 1; frac = tc - low;
    }
}

__device__ __forceinline__ __half2 h2(unsigned int u)
{
    return *reinterpret_cast<const __half2*>(&u);
}

__global__ void __launch_bounds__(256, 5)
roi_align_h2(const float* __restrict__ boxes,
             float* __restrict__ out)
{
    __shared__ int   sxl[S14], sxh[S14], syl[S14], syh[S14];  // uint4-granular
    __shared__ float sfx[S14], svx[S14], sfy[S14], svy[S14];
    __shared__ float sm[25 * SMP];                            // 26 KB staging

    const int r    = blockIdx.x;
    const int b    = r >> 9;                // 512 boxes per batch
    const int tid  = threadIdx.x;
    const int lane = tid & 31;
    const int w    = tid >> 5;

    if (tid < 32) {
        float x1 = boxes[r*4+0] * 0.25f;
        float y1 = boxes[r*4+1] * 0.25f;
        float x2 = boxes[r*4+2] * 0.25f;
        float y2 = boxes[r*4+3] * 0.25f;
        float bw = fmaxf(x2 - x1, 1.0f) * (1.0f/POUT);
        float bh = fmaxf(y2 - y1, 1.0f) * (1.0f/POUT);

        if (tid < S14) {
            float xs = x1 + ((float)tid + 0.5f) * 0.5f * bw;
            int lo, hi; float fr, vd;
            axis_prep(xs, FW, lo, hi, fr, vd);
            sxl[tid] = lo * (NCH/8);          // *32 uint4 per texel
            sxh[tid] = hi * (NCH/8);
            sfx[tid] = fr;  svx[tid] = vd;
        } else if (tid >= 16 && tid < 16 + S14) {
            int i = tid - 16;
            float ys = y1 + ((float)i + 0.5f) * 0.5f * bh;
            int lo, hi; float fr, vd;
            axis_prep(ys, FH, lo, hi, fr, vd);
            syl[i] = lo * FW * (NCH/8);
            syh[i] = hi * FW * (NCH/8);
            sfy[i] = fr;  svy[i] = vd;
        }
    }
    __syncthreads();

    const uint4* __restrict__ base =
        (const uint4*)g_nh + (size_t)b * HW * (NCH/8) + lane;

    float* const dstr = out + (size_t)r * (NCH * OPP);

#pragma unroll
    for (int chunk = 0; chunk < 2; chunk++) {
        const int pbase = chunk ? 25 : 0;
        const int pcnt  = chunk ? 24 : 25;

        for (int p = pbase + w; p < pbase + pcnt; p += 8) {
            int ph = p / POUT, pw = p - ph * POUT;
            float f0 = 0.f, f1 = 0.f, f2 = 0.f, f3 = 0.f;
            float f4 = 0.f, f5 = 0.f, f6 = 0.f, f7 = 0.f;
#pragma unroll
            for (int sy = 0; sy < 2; sy++) {
                int   iy  = 2*ph + sy;
                int   ylo = syl[iy], yhi = syh[iy];
                float fy  = sfy[iy], vy = svy[iy], hy = 1.0f - fy;
#pragma unroll
                for (int sx = 0; sx < 2; sx++) {
                    int   ix  = 2*pw + sx;
                    int   xlo = sxl[ix], xhi = sxh[ix];
                    float fx  = sfx[ix], hx = 1.0f - fx;
                    float vv  = vy * svx[ix];

                    __half2 w00 = __float2half2_rn(vv*hy*hx);
                    __half2 w01 = __float2half2_rn(vv*hy*fx);
                    __half2 w10 = __float2half2_rn(vv*fy*hx);
                    __half2 w11 = __float2half2_rn(vv*fy*fx);

                    uint4 q00 = __ldg(base + ylo + xlo);
                    uint4 q01 = __ldg(base + ylo + xhi);
                    uint4 q10 = __ldg(base + yhi + xlo);
                    uint4 q11 = __ldg(base + yhi + xhi);

                    __half2 t0 = __hmul2(w00, h2(q00.x));
                    __half2 t1 = __hmul2(w00, h2(q00.y));
                    __half2 t2 = __hmul2(w00, h2(q00.z));
                    __half2 t3 = __hmul2(w00, h2(q00.w));
                    t0 = __hfma2(w01, h2(q01.x), t0);
                    t1 = __hfma2(w01, h2(q01.y), t1);
                    t2 = __hfma2(w01, h2(q01.z), t2);
                    t3 = __hfma2(w01, h2(q01.w), t3);
                    t0 = __hfma2(w10, h2(q10.x), t0);
                    t1 = __hfma2(w10, h2(q10.y), t1);
                    t2 = __hfma2(w10, h2(q10.z), t2);
                    t3 = __hfma2(w10, h2(q10.w), t3);
                    t0 = __hfma2(w11, h2(q11.x), t0);
                    t1 = __hfma2(w11, h2(q11.y), t1);
                    t2 = __hfma2(w11, h2(q11.z), t2);
                    t3 = __hfma2(w11, h2(q11.w), t3);

                    float2 a0 = __half22float2(t0);
                    float2 a1 = __half22float2(t1);
                    float2 a2 = __half22float2(t2);
                    float2 a3 = __half22float2(t3);
                    f0 += a0.x; f1 += a0.y;
                    f2 += a1.x; f3 += a1.y;
                    f4 += a2.x; f5 += a2.y;
                    f6 += a3.x; f7 += a3.y;
                }
            }
            float4* d = (float4*)(sm + (p - pbase) * SMP + 8*lane);
            d[0] = make_float4(f0*0.25f, f1*0.25f, f2*0.25f, f3*0.25f);
            d[1] = make_float4(f4*0.25f, f5*0.25f, f6*0.25f, f7*0.25f);
        }
        __syncthreads();

        // flush chunk: out[c][pbase .. pbase+pcnt) for all 256 c
        if (chunk == 0) {
            for (int t = tid; t < NCH * 25; t += 256) {
                int c = t / 25;
                int pp = t - c * 25;
                dstr[c * OPP + pp] = sm[pp * SMP + c];
            }
        } else {
            for (int t = tid; t < NCH * 24; t += 256) {
                int c = t / 24;
                int pp = t - c * 24;
                dstr[c * OPP + 25 + pp] = sm[pp * SMP + c];
            }
        }
        __syncthreads();
    }
}

extern "C" void kernel_launch(void* const* d_in, const int* in_sizes, int n_in,
                              void* d_out, int out_size)
{
    const float* feat  = (const float*)d_in[0];
    const float* boxes = (const float*)d_in[1];
    float* out = (float*)d_out;

    const int R = out_size / (NCH * OPP);    // 1024

    dim3 tgrid(HW / 32, NCH / 64, 2);        // (1900, 4, 2)
    dim3 tblk(32, 8);
    to_nhwc_h<<<tgrid, tblk>>>(feat);

    roi_align_h2<<<R, 256>>>(boxes, out);
}

// round 6
// speedup vs baseline: 1.1571x; 1.1571x over previous
#include <cuda_runtime.h>
#include <cuda_fp16.h>

// ROI Align via fp16 NHWC relayout.
//  Pass 1: NCHW fp32 (2,256,200,304) -> NHWC fp16 scratch (62 MB, L2-resident)
//  Pass 2: block = (ROI, channel-half). 8 warps; warp = output position;
//          lane = 4 channels (uint2). Per-ROI weight/offset tables precomputed
//          in smem (196 sample-pairs); corner math in half2 (HFMA2), fp32
//          accumulation across the 4 subsamples. Outputs staged + coalesced.

#define NCH   256
#define FH    200
#define FW    304
#define HW    (FH*FW)        // 60800
#define POUT  7
#define OPP   49
#define S14   14
#define CHB   128            // channels per block
#define SMP   132            // staging pitch (floats)

__device__ unsigned int g_nh[(size_t)2 * HW * (NCH/2)];   // fp16x2 NHWC, 62 MB

// ---------------- Pass 1: NCHW fp32 -> NHWC fp16 ----------------
__global__ void __launch_bounds__(256)
to_nhwc_h(const float* __restrict__ in)
{
    __shared__ float tile[32][65];
    const int b   = blockIdx.z;
    const int c0  = blockIdx.y * 64;
    const int hw0 = blockIdx.x * 32;
    const int tx  = threadIdx.x;            // 0..31 (hw)
    const int ty  = threadIdx.y;            // 0..7  (c)

    const float* src = in + (size_t)(b * NCH + c0) * HW + hw0;
#pragma unroll
    for (int k = 0; k < 8; k++)
        tile[tx][ty + 8*k] = src[(size_t)(ty + 8*k) * HW + tx];
    __syncthreads();

    unsigned int* dst = g_nh + (size_t)(b * HW + hw0) * (NCH/2) + (c0 >> 1);
#pragma unroll
    for (int i = 0; i < 4; i++) {
        int hw = i*8 + ty;
        __half2 h = __floats2half2_rn(tile[hw][2*tx], tile[hw][2*tx + 1]);
        dst[(size_t)hw * (NCH/2) + tx] = *(unsigned int*)&h;
    }
}

// ---------------- Pass 2 ----------------
__device__ __forceinline__ void axis_prep(float t, int size,
                                          int& lo, int& hi, float& frac,
                                          float& valid)
{
    valid = (t > -1.0f && t < (float)size) ? 1.0f : 0.0f;
    float tc  = (t < 0.0f) ? 0.0f : t;
    float low = floorf(tc);
    if (low >= (float)(size - 1)) {
        lo = size - 1; hi = size - 1; frac = 0.0f;
    } else {
        lo = (int)low; hi = lo + 1; frac = tc - low;
    }
}

__device__ __forceinline__ __half2 h2(unsigned int u)
{
    return *reinterpret_cast<const __half2*>(&u);
}

__device__ __forceinline__ unsigned int rep_h2(float f)
{
    __half2 h = __float2half2_rn(f);
    return *reinterpret_cast<unsigned int*>(&h);
}

__global__ void __launch_bounds__(256, 5)
roi_align_h2t(const float* __restrict__ boxes,
              float* __restrict__ out)
{
    __shared__ int   sxl[S14], sxh[S14], syl[S14], syh[S14];  // uint2-granular
    __shared__ float sfx[S14], svx[S14], sfy[S14], svy[S14];
    __shared__ uint4 swt[196];          // 4 replicated-half2 corner weights
    __shared__ int4  soff[196];         // 4 combined corner offsets
    __shared__ float sm[OPP * SMP];     // 25.9 KB staging [p][c]

    const int r     = blockIdx.x;
    const int chalf = blockIdx.y;
    const int b     = r >> 9;                // 512 boxes per batch
    const int tid   = threadIdx.x;
    const int lane  = tid & 31;
    const int w     = tid >> 5;

    if (tid < 32) {
        float x1 = boxes[r*4+0] * 0.25f;
        float y1 = boxes[r*4+1] * 0.25f;
        float x2 = boxes[r*4+2] * 0.25f;
        float y2 = boxes[r*4+3] * 0.25f;
        float bw = fmaxf(x2 - x1, 1.0f) * (1.0f/POUT);
        float bh = fmaxf(y2 - y1, 1.0f) * (1.0f/POUT);

        if (tid < S14) {
            float xs = x1 + ((float)tid + 0.5f) * 0.5f * bw;
            int lo, hi; float fr, vd;
            axis_prep(xs, FW, lo, hi, fr, vd);
            sxl[tid] = lo * (NCH/4);          // *64 uint2 per texel
            sxh[tid] = hi * (NCH/4);
            sfx[tid] = fr;  svx[tid] = vd;
        } else if (tid >= 16 && tid < 16 + S14) {
            int i = tid - 16;
            float ys = y1 + ((float)i + 0.5f) * 0.5f * bh;
            int lo, hi; float fr, vd;
            axis_prep(ys, FH, lo, hi, fr, vd);
            syl[i] = lo * FW * (NCH/4);
            syh[i] = hi * FW * (NCH/4);
            sfy[i] = fr;  svy[i] = vd;
        }
    }
    __syncthreads();

    // build sample-pair tables: 196 = 14x14 (iy, ix)
    if (tid < 196) {
        int iy = tid / S14;
        int ix = tid - iy * S14;
        float fy = sfy[iy], hy = 1.0f - fy;
        float fx = sfx[ix], hx = 1.0f - fx;
        float vv = svy[iy] * svx[ix];
        swt[tid]  = make_uint4(rep_h2(vv*hy*hx), rep_h2(vv*hy*fx),
                               rep_h2(vv*fy*hx), rep_h2(vv*fy*fx));
        int yl = syl[iy], yh = syh[iy];
        int xl = sxl[ix], xh = sxh[ix];
        soff[tid] = make_int4(yl + xl, yl + xh, yh + xl, yh + xh);
    }
    __syncthreads();

    const uint2* __restrict__ base =
        (const uint2*)g_nh + (size_t)b * HW * (NCH/4) + chalf * 32 + lane;

    for (int p = w; p < OPP; p += 8) {
        int ph = p / POUT, pw = p - ph * POUT;
        int t00 = (2*ph) * S14 + 2*pw;           // (iy0, ix0) table index
        float f0 = 0.f, f1 = 0.f, f2 = 0.f, f3 = 0.f;
#pragma unroll
        for (int sy = 0; sy < 2; sy++) {
#pragma unroll
            for (int sx = 0; sx < 2; sx++) {
                int   idx = t00 + sy * S14 + sx;
                int4  o   = soff[idx];
                uint4 wt  = swt[idx];

                uint2 q00 = __ldg(base + o.x);
                uint2 q01 = __ldg(base + o.y);
                uint2 q10 = __ldg(base + o.z);
                uint2 q11 = __ldg(base + o.w);

                __half2 t0 = __hmul2(h2(wt.x), h2(q00.x));
                __half2 t1 = __hmul2(h2(wt.x), h2(q00.y));
                t0 = __hfma2(h2(wt.y), h2(q01.x), t0);
                t1 = __hfma2(h2(wt.y), h2(q01.y), t1);
                t0 = __hfma2(h2(wt.z), h2(q10.x), t0);
                t1 = __hfma2(h2(wt.z), h2(q10.y), t1);
                t0 = __hfma2(h2(wt.w), h2(q11.x), t0);
                t1 = __hfma2(h2(wt.w), h2(q11.y), t1);

                float2 a0 = __half22float2(t0);
                float2 a1 = __half22float2(t1);
                f0 += a0.x; f1 += a0.y;
                f2 += a1.x; f3 += a1.y;
            }
        }
        float4* d = (float4*)(sm + p * SMP + 4*lane);
        *d = make_float4(f0*0.25f, f1*0.25f, f2*0.25f, f3*0.25f);
    }
    __syncthreads();

    // flush: this block owns out[r, chalf*128 .. +128, :] = 6272 contiguous
    float* dst = out + (size_t)r * (NCH * OPP) + (size_t)chalf * (CHB * OPP);
    for (int t = tid; t < CHB * OPP; t += 256) {
        int c = t / OPP;
        int p = t - c * OPP;
        dst[t] = sm[p * SMP + c];
    }
}

extern "C" void kernel_launch(void* const* d_in, const int* in_sizes, int n_in,
                              void* d_out, int out_size)
{
    const float* feat  = (const float*)d_in[0];
    const float* boxes = (const float*)d_in[1];
    float* out = (float*)d_out;

    const int R = out_size / (NCH * OPP);    // 1024

    dim3 tgrid(HW / 32, NCH / 64, 2);        // (1900, 4, 2)
    dim3 tblk(32, 8);
    to_nhwc_h<<<tgrid, tblk>>>(feat);

    dim3 ggrid(R, 2);                        // (1024, 2)
    roi_align_h2t<<<ggrid, 256>>>(boxes, out);
}